// round 2
// baseline (speedup 1.0000x reference)
#include <cuda_runtime.h>

namespace {
constexpr int B  = 2;
constexpr int C  = 32;
constexpr int H  = 192;
constexpr int W  = 256;
constexpr int JH = 12;
constexpr int JW = 16;
constexpr int J  = JH * JW;      // 192
constexpr int N  = H * W;        // 49152
constexpr int HW = H * W;
constexpr int PITCH = 257;       // conflict-free pitch for pix_sh
}

// Persistent scratch (device globals; no allocation allowed)
__device__ float g_spix[B * J * C];
__device__ float g_num[2][B * J * C];   // ping-pong accumulators
__device__ float g_den[2][B * J];
__device__ float g_aff[B * 9 * N];      // affinities of iteration 10
__device__ float g_fm[B * J * C];       // feat_map_J

// ---------------------------------------------------------------------------
// Initial superpixel features: mean over each 16x16 cell
// ---------------------------------------------------------------------------
__global__ void k_init_spix(const float* __restrict__ feats) {
    int blk = blockIdx.x;
    int b = blk / J, j = blk % J;
    int jy = j / JW, jx = j % JW;
    int t = threadIdx.x;
    int py = t >> 4, px = t & 15;
    int y = jy * 16 + py, x = jx * 16 + px;
    const float* base = feats + (size_t)b * C * HW + y * W + x;

    __shared__ float part[8][C + 1];
    int w = t >> 5, lane = t & 31;
    #pragma unroll
    for (int c = 0; c < C; c++) {
        float v = base[c * HW];
        #pragma unroll
        for (int o = 16; o; o >>= 1) v += __shfl_xor_sync(0xffffffffu, v, o);
        if (lane == 0) part[w][c] = v;
    }
    __syncthreads();
    if (t < C) {
        float s = 0.0f;
        #pragma unroll
        for (int ww = 0; ww < 8; ww++) s += part[ww][t];
        g_spix[(b * J + j) * C + t] = s * (1.0f / 256.0f);
    }
}

// ---------------------------------------------------------------------------
// Zero accumulator buffer 0 (buffer 1 is zeroed by the normalize chain)
// ---------------------------------------------------------------------------
__global__ void k_zero0() {
    int i = blockIdx.x * blockDim.x + threadIdx.x;
    if (i < B * J * C) g_num[0][i] = 0.0f;
    if (i < B * J)     g_den[0][i] = 0.0f;
}

// ---------------------------------------------------------------------------
// One SSN iteration. One CTA per (b, cell). 288 threads = 9 warps.
// Phase 1 (256 threads): per-pixel distances to 9 neighbor spix, softmax.
// Phase 2 (9 warps): warp k reduces aff_k * pix over the 256 pixels and
// atomically accumulates into the neighbor cell's (num, den).
// ---------------------------------------------------------------------------
__global__ __launch_bounds__(288) void k_iterate(const float* __restrict__ feats,
                                                 int buf, int storeAff) {
    __shared__ float s_sh[9][C];
    __shared__ float sn_sh[9];
    __shared__ int   cell_sh[9];
    __shared__ float pix_sh[C][PITCH];
    __shared__ __align__(16) float aff_sh[9][256];

    int blk = blockIdx.x;
    int b = blk / J, j = blk % J;
    int jy = j / JW, jx = j % JW;
    int t = threadIdx.x;
    int wk = t >> 5, lane = t & 31;

    // phase 0: load neighbor spix (coalesced: [b][j][c] layout) + norms
    {
        int dy = wk / 3 - 1, dx = wk % 3 - 1;
        int ny = jy + dy, nx = jx + dx;
        int nc = (ny >= 0 && ny < JH && nx >= 0 && nx < JW) ? ny * JW + nx : -1;
        if (lane == 0) cell_sh[wk] = nc;
        float sv = (nc >= 0) ? g_spix[(b * J + nc) * C + lane] : 0.0f;
        s_sh[wk][lane] = sv;
        float sq = sv * sv;
        #pragma unroll
        for (int o = 16; o; o >>= 1) sq += __shfl_xor_sync(0xffffffffu, sq, o);
        if (lane == 0) sn_sh[wk] = sq;
    }

    // phase 1 global loads (issued before the barrier to hide latency)
    float f[C];
    int n = 0;
    if (t < 256) {
        int py = t >> 4, px = t & 15;
        int y = jy * 16 + py, x = jx * 16 + px;
        n = y * W + x;
        const float* fp = feats + (size_t)b * C * HW + n;
        #pragma unroll
        for (int c = 0; c < C; c++) {
            f[c] = fp[c * HW];
            pix_sh[c][t] = f[c];
        }
    }
    __syncthreads();

    if (t < 256) {
        float fn = 0.0f;
        #pragma unroll
        for (int c = 0; c < C; c++) fn += f[c] * f[c];

        float dist[9];
        #pragma unroll
        for (int k = 0; k < 9; k++) {
            float dot = 0.0f;
            #pragma unroll
            for (int c = 0; c < C; c++) dot += f[c] * s_sh[k][c];
            dist[k] = fn - 2.0f * dot + sn_sh[k];
        }
        float m = 3.0e38f;
        #pragma unroll
        for (int k = 0; k < 9; k++)
            if (cell_sh[k] >= 0) m = fminf(m, dist[k]);
        float e[9];
        float sum = 0.0f;
        #pragma unroll
        for (int k = 0; k < 9; k++) {
            e[k] = (cell_sh[k] >= 0) ? __expf(m - dist[k]) : 0.0f;
            sum += e[k];
        }
        float inv = 1.0f / sum;
        #pragma unroll
        for (int k = 0; k < 9; k++) {
            float a = e[k] * inv;
            aff_sh[k][t] = a;
            if (storeAff) g_aff[(b * 9 + k) * N + n] = a;
        }
    }
    __syncthreads();

    // phase 2: warp wk accumulates into neighbor cell cell_sh[wk]
    int nc = cell_sh[wk];
    if (nc >= 0) {
        const float* ar = aff_sh[wk];
        const float* pr = pix_sh[lane];   // row for this lane's channel

        // denominator: sum of affinities (lane-parallel, then shfl reduce)
        float dp = 0.0f;
        #pragma unroll
        for (int i = 0; i < 8; i++) dp += ar[lane + (i << 5)];
        #pragma unroll
        for (int o = 16; o; o >>= 1) dp += __shfl_xor_sync(0xffffffffu, dp, o);

        // numerator: acc[c] = sum_p aff[p] * pix[c][p]
        float a0 = 0, a1 = 0, a2 = 0, a3 = 0;
        #pragma unroll 8
        for (int p = 0; p < 256; p += 4) {
            const float4 av = *(const float4*)&ar[p];
            a0 += av.x * pr[p];
            a1 += av.y * pr[p + 1];
            a2 += av.z * pr[p + 2];
            a3 += av.w * pr[p + 3];
        }
        float acc = (a0 + a1) + (a2 + a3);
        atomicAdd(&g_num[buf][(b * J + nc) * C + lane], acc);
        if (lane == 0) atomicAdd(&g_den[buf][b * J + nc], dp);
    }
}

// ---------------------------------------------------------------------------
// spix[b][j][c] = num / (den + 1e-16); zero the *other* buffer for next iter
// ---------------------------------------------------------------------------
__global__ void k_normalize(int buf, int zbuf) {
    int i = blockIdx.x * blockDim.x + threadIdx.x;
    if (i < B * J * C) {
        g_spix[i] = g_num[buf][i] / (g_den[buf][i / C] + 1e-16f);
        g_num[zbuf][i] = 0.0f;
    }
    if (i < B * J) g_den[zbuf][i] = 0.0f;
}

// feat_map_J = num / (den + 1e-6)   (Q_M normalization)
__global__ void k_finalize_fm(int buf) {
    int i = blockIdx.x * blockDim.x + threadIdx.x;
    if (i < B * J * C)
        g_fm[i] = g_num[buf][i] / (g_den[buf][i / C] + 1e-6f);
}

// ---------------------------------------------------------------------------
// Final outputs. One CTA per (b, image row y), 256 threads (one per x).
//   recon[b,c,n] = sum_k aff_k(n) * fm[cell_k(n)][c]
//   gamma[b,j,n] = aff_k if j is the k-th neighbor of pixel n else 0
// Gamma written as float4 rows (fully coalesced, covers all 192 planes).
// ---------------------------------------------------------------------------
__global__ __launch_bounds__(256) void k_final(float* __restrict__ gamma_out,
                                               float* __restrict__ recon_out) {
    __shared__ float fm_sh[3 * JW * C];                 // 3 cell-rows of fm
    __shared__ __align__(16) float aff_row[9][256];

    int blk = blockIdx.x;
    int b = blk / H, y = blk % H;
    int iy = y >> 4;
    int x = threadIdx.x;
    int n = y * W + x;

    for (int tt = threadIdx.x; tt < 3 * JW * C; tt += 256) {
        int r = tt / (JW * C), rem = tt - r * (JW * C);
        int ry = iy - 1 + r;
        ry = min(max(ry, 0), JH - 1);                   // clamped; unused rows get aff=0
        fm_sh[tt] = g_fm[(b * J + ry * JW) * C + rem];
    }
    float aff[9];
    #pragma unroll
    for (int k = 0; k < 9; k++) {
        aff[k] = g_aff[(b * 9 + k) * N + n];
        aff_row[k][x] = aff[k];
    }
    __syncthreads();

    // reconstruction
    int jx = x >> 4;
    float rec[C];
    #pragma unroll
    for (int c = 0; c < C; c++) rec[c] = 0.0f;
    #pragma unroll
    for (int k = 0; k < 9; k++) {
        int dy = k / 3 - 1, dx = k % 3 - 1;
        int r  = dy + 1;
        int cx = min(max(jx + dx, 0), JW - 1);          // clamped; aff=0 if invalid
        const float* fm = &fm_sh[(r * JW + cx) * C];
        float a = aff[k];
        #pragma unroll
        for (int c = 0; c < C; c++) rec[c] += a * fm[c];
    }
    #pragma unroll
    for (int c = 0; c < C; c++)
        recon_out[((size_t)(b * C + c) * H + y) * W + x] = rec[c];

    // gamma: thread covers pixel-quad q for j-planes jr, jr+4, ..., jr+188
    int q = x & 63, jr = x >> 6;
    int pjx = q >> 2;                                   // cell of the 4-pixel group
    #pragma unroll 4
    for (int i = 0; i < 48; i++) {
        int jv  = jr + (i << 2);
        int jjy = jv >> 4, jjx = jv & 15;
        int ddy = jjy - iy, ddx = jjx - pjx;
        float4 v = make_float4(0.f, 0.f, 0.f, 0.f);
        if (ddy >= -1 && ddy <= 1 && ddx >= -1 && ddx <= 1) {
            int k = (ddy + 1) * 3 + (ddx + 1);
            v = *(const float4*)&aff_row[k][q << 2];
        }
        *(float4*)&gamma_out[(size_t)(b * J + jv) * N + y * W + (q << 2)] = v;
    }
}

// ---------------------------------------------------------------------------
extern "C" void kernel_launch(void* const* d_in, const int* in_sizes, int n_in,
                              void* d_out, int out_size) {
    (void)in_sizes; (void)n_in; (void)out_size;
    const float* feats = (const float*)d_in[0];
    float* gamma = (float*)d_out;
    float* recon = gamma + (size_t)B * J * N;

    k_init_spix<<<B * J, 256>>>(feats);
    k_zero0<<<(B * J * C + 255) / 256, 256>>>();

    for (int it = 0; it < 10; it++) {
        int buf = it & 1;
        k_iterate<<<B * J, 288>>>(feats, buf, it == 9 ? 1 : 0);
        if (it < 9) k_normalize<<<48, 256>>>(buf, buf ^ 1);
    }
    k_finalize_fm<<<48, 256>>>(1);
    k_final<<<B * H, 256>>>(gamma, recon);
}

// round 3
// speedup vs baseline: 1.3000x; 1.3000x over previous
#include <cuda_runtime.h>

namespace {
constexpr int B  = 2;
constexpr int C  = 32;
constexpr int H  = 192;
constexpr int W  = 256;
constexpr int JH = 12;
constexpr int JW = 16;
constexpr int J  = JH * JW;      // 192
constexpr int N  = H * W;        // 49152
constexpr int HW = H * W;
constexpr int NITER = 10;
constexpr int PITCH = 260;       // %4==0 (16B-aligned rows) and 4l+p mod 32 distinct -> LDS.128 conflict-free
}

// Persistent scratch (device globals; no allocation allowed)
__device__ float g_spix[B * J * C];
__device__ float g_num[NITER][B * J * C];   // per-iteration accumulators (zeroed once in k_init)
__device__ float g_den[NITER][B * J];
__device__ float g_aff[B * 9 * N];          // affinities of iteration 10

// ---------------------------------------------------------------------------
// Initial superpixel features (mean over each 16x16 cell) + zero accumulators
// ---------------------------------------------------------------------------
__global__ void k_init(const float* __restrict__ feats) {
    int blk = blockIdx.x;
    int b = blk / J, j = blk % J;
    int jy = j / JW, jx = j % JW;
    int t = threadIdx.x;
    int py = t >> 4, px = t & 15;
    int y = jy * 16 + py, x = jx * 16 + px;
    const float* base = feats + (size_t)b * C * HW + y * W + x;

    __shared__ float part[8][C + 1];
    int w = t >> 5, lane = t & 31;
    #pragma unroll
    for (int c = 0; c < C; c++) {
        float v = base[c * HW];
        #pragma unroll
        for (int o = 16; o; o >>= 1) v += __shfl_xor_sync(0xffffffffu, v, o);
        if (lane == 0) part[w][c] = v;
    }
    __syncthreads();
    if (t < C) {
        float s = 0.0f;
        #pragma unroll
        for (int ww = 0; ww < 8; ww++) s += part[ww][t];
        g_spix[(b * J + j) * C + t] = s * (1.0f / 256.0f);
    }

    // zero all per-iteration accumulators (grid-stride over the whole grid)
    int gtid = blk * 256 + t;
    float* numf = &g_num[0][0];
    for (int i = gtid; i < NITER * B * J * C; i += J * B * 256)
        numf[i] = 0.0f;
    float* denf = &g_den[0][0];
    if (gtid < NITER * B * J) denf[gtid] = 0.0f;
}

// ---------------------------------------------------------------------------
// One SSN iteration. One CTA per (b, cell). 256 threads = 8 warps.
// Reads spix implicitly: it==0 -> g_spix, else num[it-1]/(den[it-1]+1e-16).
// Phase 1: per-pixel distances to 9 neighbor spix, softmax (one thread = one px).
// Phase 2: warp w covers pixel slice [32w,32w+32); lane = channel; acc[9] in
// registers; 8-way smem tree reduce; one atomic per (neighbor, channel).
// ---------------------------------------------------------------------------
__global__ __launch_bounds__(256, 3) void k_iterate(const float* __restrict__ feats,
                                                    int it) {
    __shared__ float s_sh[9][C];
    __shared__ float sn_sh[9];
    __shared__ int   cell_sh[9];
    __shared__ __align__(16) float pix_sh[C * PITCH];   // aliased by s_acc in reduce phase
    __shared__ __align__(16) float aff_sh[9][256];

    int blk = blockIdx.x;
    int b = blk / J, j = blk % J;
    int jy = j / JW, jx = j % JW;
    int t = threadIdx.x;
    int wk = t >> 5, lane = t & 31;

    // phase 0: neighbor spix (coalesced) + squared norms. warp w -> k=w; warp 0 also k=8.
    for (int k = wk; k < 9; k += 8) {
        int dy = k / 3 - 1, dx = k % 3 - 1;
        int ny = jy + dy, nx = jx + dx;
        int nc = (ny >= 0 && ny < JH && nx >= 0 && nx < JW) ? ny * JW + nx : -1;
        if (lane == 0) cell_sh[k] = nc;
        float sv = 0.0f;
        if (nc >= 0) {
            if (it == 0)
                sv = g_spix[(b * J + nc) * C + lane];
            else
                sv = g_num[it - 1][(b * J + nc) * C + lane] /
                     (g_den[it - 1][b * J + nc] + 1e-16f);
        }
        s_sh[k][lane] = sv;
        float sq = sv * sv;
        #pragma unroll
        for (int o = 16; o; o >>= 1) sq += __shfl_xor_sync(0xffffffffu, sq, o);
        if (lane == 0) sn_sh[k] = sq;
    }

    // phase 1 pixel loads (before barrier, hide latency)
    int py = t >> 4, px = t & 15;
    int y = jy * 16 + py, x = jx * 16 + px;
    int n = y * W + x;
    const float* fp = feats + (size_t)b * C * HW + n;
    float f[C];
    #pragma unroll
    for (int c = 0; c < C; c++) {
        f[c] = fp[c * HW];
        pix_sh[c * PITCH + t] = f[c];
    }
    __syncthreads();

    // distances + softmax
    float fn = 0.0f;
    #pragma unroll
    for (int c = 0; c < C; c++) fn += f[c] * f[c];

    float dist[9];
    #pragma unroll
    for (int k = 0; k < 9; k++) {
        float dot = 0.0f;
        #pragma unroll
        for (int c = 0; c < C; c++) dot += f[c] * s_sh[k][c];
        dist[k] = fn - 2.0f * dot + sn_sh[k];
    }
    float m = 3.0e38f;
    #pragma unroll
    for (int k = 0; k < 9; k++)
        if (cell_sh[k] >= 0) m = fminf(m, dist[k]);
    float e[9];
    float sum = 0.0f;
    #pragma unroll
    for (int k = 0; k < 9; k++) {
        e[k] = (cell_sh[k] >= 0) ? __expf(m - dist[k]) : 0.0f;
        sum += e[k];
    }
    float inv = 1.0f / sum;
    #pragma unroll
    for (int k = 0; k < 9; k++) {
        float a = e[k] * inv;
        aff_sh[k][t] = a;
        if (it == NITER - 1) g_aff[(b * 9 + k) * N + n] = a;
    }
    __syncthreads();

    // phase 2: slice accumulation. lane = channel, warp slice = pixels [32wk, 32wk+32)
    float acc[9];
    #pragma unroll
    for (int k = 0; k < 9; k++) acc[k] = 0.0f;
    {
        int p0 = wk * 32;
        const float* pr = &pix_sh[lane * PITCH + p0];
        #pragma unroll
        for (int i = 0; i < 32; i += 4) {
            float4 pv = *(const float4*)&pr[i];
            #pragma unroll
            for (int k = 0; k < 9; k++) {
                float4 av = *(const float4*)&aff_sh[k][p0 + i];   // broadcast
                acc[k] += av.x * pv.x + av.y * pv.y + av.z * pv.z + av.w * pv.w;
            }
        }
    }
    __syncthreads();                     // all pix_sh reads done; safe to alias
    float* s_acc = pix_sh;               // [8][9][32]
    #pragma unroll
    for (int k = 0; k < 9; k++)
        s_acc[(wk * 9 + k) * 32 + lane] = acc[k];
    __syncthreads();

    // reduce + atomics: warp w -> k=w; warp 0 also k=8
    for (int k = wk; k < 9; k += 8) {
        int nc = cell_sh[k];
        if (nc >= 0) {
            float v = 0.0f;
            #pragma unroll
            for (int ww = 0; ww < 8; ww++)
                v += s_acc[(ww * 9 + k) * 32 + lane];
            atomicAdd(&g_num[it][(b * J + nc) * C + lane], v);

            float d = 0.0f;
            #pragma unroll
            for (int i2 = 0; i2 < 8; i2++)
                d += aff_sh[k][lane + (i2 << 5)];
            #pragma unroll
            for (int o = 16; o; o >>= 1) d += __shfl_xor_sync(0xffffffffu, d, o);
            if (lane == 0) atomicAdd(&g_den[it][b * J + nc], d);
        }
    }
}

// ---------------------------------------------------------------------------
// Final outputs. One CTA per (b, image row y), 256 threads (one per x).
//   fm[j][c] = num[9]/(den[9]+1e-6)   (computed on load)
//   recon[b,c,n] = sum_k aff_k(n) * fm[cell_k(n)][c]
//   gamma[b,j,n] = aff_k if j is the k-th neighbor of pixel n else 0
// ---------------------------------------------------------------------------
__global__ __launch_bounds__(256) void k_final(float* __restrict__ gamma_out,
                                               float* __restrict__ recon_out) {
    __shared__ float fm_sh[3 * JW * C];                 // 3 cell-rows of fm
    __shared__ __align__(16) float aff_row[9][256];

    int blk = blockIdx.x;
    int b = blk / H, y = blk % H;
    int iy = y >> 4;
    int x = threadIdx.x;
    int n = y * W + x;

    for (int tt = threadIdx.x; tt < 3 * JW * C; tt += 256) {
        int r = tt / (JW * C), rem = tt - r * (JW * C);
        int ry = iy - 1 + r;
        ry = min(max(ry, 0), JH - 1);                   // clamped; unused rows get aff=0
        int cell = ry * JW + (rem >> 5);                // rem/C
        fm_sh[tt] = g_num[NITER - 1][(b * J + cell) * C + (rem & 31)] /
                    (g_den[NITER - 1][b * J + cell] + 1e-6f);
    }
    float aff[9];
    #pragma unroll
    for (int k = 0; k < 9; k++) {
        aff[k] = g_aff[(b * 9 + k) * N + n];
        aff_row[k][x] = aff[k];
    }
    __syncthreads();

    // reconstruction
    int jx = x >> 4;
    float rec[C];
    #pragma unroll
    for (int c = 0; c < C; c++) rec[c] = 0.0f;
    #pragma unroll
    for (int k = 0; k < 9; k++) {
        int dy = k / 3 - 1, dx = k % 3 - 1;
        int r  = dy + 1;
        int cx = min(max(jx + dx, 0), JW - 1);          // clamped; aff=0 if invalid
        const float* fm = &fm_sh[(r * JW + cx) * C];
        float a = aff[k];
        #pragma unroll
        for (int c = 0; c < C; c++) rec[c] += a * fm[c];
    }
    #pragma unroll
    for (int c = 0; c < C; c++)
        __stcs(&recon_out[((size_t)(b * C + c) * H + y) * W + x], rec[c]);

    // gamma: thread covers pixel-quad q for j-planes jr, jr+4, ..., jr+188
    int q = x & 63, jr = x >> 6;
    int pjx = q >> 2;                                   // cell of the 4-pixel group
    #pragma unroll 4
    for (int i = 0; i < 48; i++) {
        int jv  = jr + (i << 2);
        int jjy = jv >> 4, jjx = jv & 15;
        int ddy = jjy - iy, ddx = jjx - pjx;
        float4 v = make_float4(0.f, 0.f, 0.f, 0.f);
        if (ddy >= -1 && ddy <= 1 && ddx >= -1 && ddx <= 1) {
            int k = (ddy + 1) * 3 + (ddx + 1);
            v = *(const float4*)&aff_row[k][q << 2];
        }
        __stcs((float4*)&gamma_out[(size_t)(b * J + jv) * N + y * W + (q << 2)], v);
    }
}

// ---------------------------------------------------------------------------
extern "C" void kernel_launch(void* const* d_in, const int* in_sizes, int n_in,
                              void* d_out, int out_size) {
    (void)in_sizes; (void)n_in; (void)out_size;
    const float* feats = (const float*)d_in[0];
    float* gamma = (float*)d_out;
    float* recon = gamma + (size_t)B * J * N;

    k_init<<<B * J, 256>>>(feats);
    for (int it = 0; it < NITER; it++)
        k_iterate<<<B * J, 256>>>(feats, it);
    k_final<<<B * H, 256>>>(gamma, recon);
}

// round 4
// speedup vs baseline: 1.3423x; 1.0325x over previous
#include <cuda_runtime.h>

namespace {
constexpr int B  = 2;
constexpr int C  = 32;
constexpr int H  = 192;
constexpr int W  = 256;
constexpr int JH = 12;
constexpr int JW = 16;
constexpr int J  = JH * JW;      // 192
constexpr int N  = H * W;        // 49152
constexpr int HW = H * W;
constexpr int NITER = 10;
constexpr int PITCH = 260;       // 16B-aligned rows; LDS.128 conflict-free per 8-lane phase
constexpr int NB = B * J;        // 384 blocks, all co-resident at 3 CTAs/SM
}

// Persistent scratch (device globals; no allocation allowed)
__device__ float g_spix[B * J * C];
__device__ float g_num[NITER][B * J * C];
__device__ float g_den[NITER][B * J];
__device__ float g_aff[B * 9 * N];
__device__ unsigned g_cnt;       // zero-init; restored to 0 by every barrier release
__device__ unsigned g_gen;       // monotonically increasing generation (wrap-safe, == compare)

// ---------------------------------------------------------------------------
// Software grid barrier. Safe because all NB blocks are co-resident
// (grid 384 <= 148 SMs * 3 CTAs guaranteed by __launch_bounds__(256,3)).
// ---------------------------------------------------------------------------
__device__ __forceinline__ void grid_barrier() {
    __syncthreads();
    if (threadIdx.x == 0) {
        __threadfence();
        unsigned mygen = atomicAdd(&g_gen, 0u);      // snapshot BEFORE arriving
        unsigned old   = atomicAdd(&g_cnt, 1u);
        if (old == NB - 1) {
            atomicExch(&g_cnt, 0u);
            __threadfence();
            atomicAdd(&g_gen, 1u);                   // release
        } else {
            while (atomicAdd(&g_gen, 0u) == mygen) __nanosleep(64);
        }
        __threadfence();
    }
    __syncthreads();
}

// ---------------------------------------------------------------------------
// Fused SSN: init + 10 iterations in one persistent kernel.
// One CTA per (b, cell); 256 threads; pixel tile resident in smem/regs.
// ---------------------------------------------------------------------------
__global__ __launch_bounds__(256, 3) void k_fused(const float* __restrict__ feats) {
    __shared__ float s_sh[9][C];
    __shared__ float sn_sh[9];
    __shared__ int   cell_sh[9];
    __shared__ __align__(16) float pix_sh[C * PITCH];   // persists across iterations
    __shared__ __align__(16) float aff_sh[9][256];      // re-used as s_acc in reduce

    int blk = blockIdx.x;
    int b = blk / J, j = blk % J;
    int jy = j / JW, jx = j % JW;
    int t = threadIdx.x;
    int wk = t >> 5, lane = t & 31;

    // neighbor cell table (constant across iterations)
    if (t < 9) {
        int dy = t / 3 - 1, dx = t % 3 - 1;
        int ny = jy + dy, nx = jx + dx;
        cell_sh[t] = (ny >= 0 && ny < JH && nx >= 0 && nx < JW) ? ny * JW + nx : -1;
    }

    // load pixel features ONCE; keep in registers + smem
    int py = t >> 4, px = t & 15;
    int y = jy * 16 + py, x = jx * 16 + px;
    int n = y * W + x;
    const float* fp = feats + (size_t)b * C * HW + n;
    float f[C];
    #pragma unroll
    for (int c = 0; c < C; c++) {
        f[c] = fp[c * HW];
        pix_sh[c * PITCH + t] = f[c];
    }
    float fn = 0.0f;
    #pragma unroll
    for (int c = 0; c < C; c++) fn += f[c] * f[c];

    // zero this cell's accumulators for all iterations
    if (t < C) {
        #pragma unroll
        for (int it = 0; it < NITER; it++) g_num[it][(b * J + j) * C + t] = 0.0f;
    }
    if (t == C) {
        #pragma unroll
        for (int it = 0; it < NITER; it++) g_den[it][b * J + j] = 0.0f;
    }
    __syncthreads();   // pix_sh + cell_sh ready

    // initial spix = mean over own 16x16 cell (warp slices -> tree)
    {
        const float* pr = &pix_sh[lane * PITCH + wk * 32];
        float ms = 0.0f;
        #pragma unroll
        for (int i = 0; i < 32; i += 4) {
            float4 v = *(const float4*)&pr[i];
            ms += (v.x + v.y) + (v.z + v.w);
        }
        ((float*)aff_sh)[wk * 32 + lane] = ms;
        __syncthreads();
        if (wk == 0) {
            float s = 0.0f;
            #pragma unroll
            for (int w2 = 0; w2 < 8; w2++) s += ((float*)aff_sh)[w2 * 32 + lane];
            g_spix[(b * J + j) * C + lane] = s * (1.0f / 256.0f);
        }
    }
    grid_barrier();

    for (int it = 0; it < NITER; it++) {
        // phase 0: neighbor spix (it==0: cell means; else num/(den+1e-16)) + norms
        for (int k = wk; k < 9; k += 8) {
            int nc = cell_sh[k];
            float sv = 0.0f;
            if (nc >= 0) {
                if (it == 0)
                    sv = g_spix[(b * J + nc) * C + lane];
                else
                    sv = g_num[it - 1][(b * J + nc) * C + lane] /
                         (g_den[it - 1][b * J + nc] + 1e-16f);
            }
            s_sh[k][lane] = sv;
            float sq = sv * sv;
            #pragma unroll
            for (int o = 16; o; o >>= 1) sq += __shfl_xor_sync(0xffffffffu, sq, o);
            if (lane == 0) sn_sh[k] = sq;
        }
        __syncthreads();

        // phase 1: distances (LDS.128 broadcast of s) + masked softmax
        float dist[9];
        #pragma unroll
        for (int k = 0; k < 9; k++) {
            const float4* s4 = (const float4*)s_sh[k];
            float d0 = 0, d1 = 0, d2 = 0, d3 = 0;
            #pragma unroll
            for (int c4 = 0; c4 < 8; c4++) {
                float4 sv = s4[c4];
                d0 += f[4 * c4 + 0] * sv.x;
                d1 += f[4 * c4 + 1] * sv.y;
                d2 += f[4 * c4 + 2] * sv.z;
                d3 += f[4 * c4 + 3] * sv.w;
            }
            dist[k] = fn - 2.0f * ((d0 + d1) + (d2 + d3)) + sn_sh[k];
        }
        float m = 3.0e38f;
        #pragma unroll
        for (int k = 0; k < 9; k++)
            if (cell_sh[k] >= 0) m = fminf(m, dist[k]);
        float a[9];
        float sum = 0.0f;
        #pragma unroll
        for (int k = 0; k < 9; k++) {
            a[k] = (cell_sh[k] >= 0) ? __expf(m - dist[k]) : 0.0f;
            sum += a[k];
        }
        float inv = 1.0f / sum;
        #pragma unroll
        for (int k = 0; k < 9; k++) {
            a[k] *= inv;
            aff_sh[k][t] = a[k];
        }
        if (it == NITER - 1) {
            #pragma unroll
            for (int k = 0; k < 9; k++)
                g_aff[(b * 9 + k) * N + n] = a[k];
        }
        __syncthreads();

        // phase 2: warp slice accumulation (lane = channel)
        float acc[9];
        #pragma unroll
        for (int k = 0; k < 9; k++) acc[k] = 0.0f;
        {
            int p0 = wk * 32;
            const float* pr = &pix_sh[lane * PITCH + p0];
            #pragma unroll
            for (int i = 0; i < 32; i += 4) {
                float4 pv = *(const float4*)&pr[i];
                #pragma unroll
                for (int k = 0; k < 9; k++) {
                    float4 av = *(const float4*)&aff_sh[k][p0 + i];   // broadcast
                    acc[k] += av.x * pv.x + av.y * pv.y + av.z * pv.z + av.w * pv.w;
                }
            }
        }
        // denominators: warp k sums aff_sh[k] (reads before aff_sh is overwritten)
        for (int k = wk; k < 9; k += 8) {
            int nc = cell_sh[k];
            if (nc >= 0) {
                float d = 0.0f;
                #pragma unroll
                for (int i2 = 0; i2 < 8; i2++) d += aff_sh[k][lane + (i2 << 5)];
                #pragma unroll
                for (int o = 16; o; o >>= 1) d += __shfl_xor_sync(0xffffffffu, d, o);
                if (lane == 0) atomicAdd(&g_den[it][b * J + nc], d);
            }
        }
        __syncthreads();                       // all aff_sh reads done -> safe to alias
        float* s_acc = (float*)aff_sh;         // [8][9][32]
        #pragma unroll
        for (int k = 0; k < 9; k++)
            s_acc[(wk * 9 + k) * 32 + lane] = acc[k];
        __syncthreads();

        // tree reduce + one atomic per (neighbor, channel)
        for (int k = wk; k < 9; k += 8) {
            int nc = cell_sh[k];
            if (nc >= 0) {
                float v = 0.0f;
                #pragma unroll
                for (int w2 = 0; w2 < 8; w2++)
                    v += s_acc[(w2 * 9 + k) * 32 + lane];
                atomicAdd(&g_num[it][(b * J + nc) * C + lane], v);
            }
        }
        if (it < NITER - 1) grid_barrier();
    }
}

// ---------------------------------------------------------------------------
// Final outputs. One CTA per (b, image row y), 256 threads (one per x).
//   fm[j][c] = num[9]/(den[9]+1e-6)  (computed on load)
//   recon[b,c,n] = sum_k aff_k(n) * fm[cell_k(n)][c]
//   gamma[b,j,n] = aff_k if j is the k-th neighbor of pixel n else 0
// ---------------------------------------------------------------------------
__global__ __launch_bounds__(256) void k_final(float* __restrict__ gamma_out,
                                               float* __restrict__ recon_out) {
    __shared__ float fm_sh[3 * JW * C];
    __shared__ __align__(16) float aff_row[9][256];

    int blk = blockIdx.x;
    int b = blk / H, y = blk % H;
    int iy = y >> 4;
    int x = threadIdx.x;
    int n = y * W + x;

    for (int tt = threadIdx.x; tt < 3 * JW * C; tt += 256) {
        int r = tt / (JW * C), rem = tt - r * (JW * C);
        int ry = iy - 1 + r;
        ry = min(max(ry, 0), JH - 1);
        int cell = ry * JW + (rem >> 5);
        fm_sh[tt] = g_num[NITER - 1][(b * J + cell) * C + (rem & 31)] /
                    (g_den[NITER - 1][b * J + cell] + 1e-6f);
    }
    float aff[9];
    #pragma unroll
    for (int k = 0; k < 9; k++) {
        aff[k] = g_aff[(b * 9 + k) * N + n];
        aff_row[k][x] = aff[k];
    }
    __syncthreads();

    int jx = x >> 4;
    float rec[C];
    #pragma unroll
    for (int c = 0; c < C; c++) rec[c] = 0.0f;
    #pragma unroll
    for (int k = 0; k < 9; k++) {
        int dy = k / 3 - 1, dx = k % 3 - 1;
        int r  = dy + 1;
        int cx = min(max(jx + dx, 0), JW - 1);
        const float* fm = &fm_sh[(r * JW + cx) * C];
        float ak = aff[k];
        #pragma unroll
        for (int c = 0; c < C; c++) rec[c] += ak * fm[c];
    }
    #pragma unroll
    for (int c = 0; c < C; c++)
        __stcs(&recon_out[((size_t)(b * C + c) * H + y) * W + x], rec[c]);

    int q = x & 63, jr = x >> 6;
    int pjx = q >> 2;
    #pragma unroll 4
    for (int i = 0; i < 48; i++) {
        int jv  = jr + (i << 2);
        int jjy = jv >> 4, jjx = jv & 15;
        int ddy = jjy - iy, ddx = jjx - pjx;
        float4 v = make_float4(0.f, 0.f, 0.f, 0.f);
        if (ddy >= -1 && ddy <= 1 && ddx >= -1 && ddx <= 1) {
            int k = (ddy + 1) * 3 + (ddx + 1);
            v = *(const float4*)&aff_row[k][q << 2];
        }
        __stcs((float4*)&gamma_out[(size_t)(b * J + jv) * N + y * W + (q << 2)], v);
    }
}

// ---------------------------------------------------------------------------
extern "C" void kernel_launch(void* const* d_in, const int* in_sizes, int n_in,
                              void* d_out, int out_size) {
    (void)in_sizes; (void)n_in; (void)out_size;
    const float* feats = (const float*)d_in[0];
    float* gamma = (float*)d_out;
    float* recon = gamma + (size_t)B * J * N;

    k_fused<<<NB, 256>>>(feats);
    k_final<<<B * H, 256>>>(gamma, recon);
}

// round 5
// speedup vs baseline: 1.5547x; 1.1582x over previous
#include <cuda_runtime.h>

namespace {
constexpr int B  = 2;
constexpr int C  = 32;
constexpr int H  = 192;
constexpr int W  = 256;
constexpr int JH = 12;
constexpr int JW = 16;
constexpr int J  = JH * JW;      // 192
constexpr int N  = H * W;        // 49152
constexpr int HW = H * W;
constexpr int NITER = 10;
constexpr int SLOTS = NITER + 1; // slot 0 = init, slots 1..10 = iteration results
constexpr int PITCH = 260;       // 16B-aligned rows; LDS.128 conflict-free
constexpr int NB = B * J;        // 384 blocks, all co-resident at 3 CTAs/SM
}

// Persistent scratch (device globals; no allocation allowed)
__device__ float    g_num[SLOTS][B * J * C];
__device__ float    g_den[SLOTS][B * J];
__device__ unsigned g_flag[SLOTS][B * J];

// ---------------------------------------------------------------------------
// Reset the dataflow flags each replay (kernel boundary orders it vs k_fused).
// ---------------------------------------------------------------------------
__global__ void k_reset() {
    int i = blockIdx.x * blockDim.x + threadIdx.x;
    if (i < SLOTS * B * J) (&g_flag[0][0])[i] = 0u;
}

__device__ __forceinline__ void poll_flag(const unsigned* p, unsigned expect) {
    unsigned v;
    do {
        asm volatile("ld.acquire.gpu.u32 %0, [%1];" : "=r"(v) : "l"(p) : "memory");
        if (v >= expect) return;
        __nanosleep(64);
    } while (true);
}

// ---------------------------------------------------------------------------
// Fully fused SSN: init + 10 iterations + final outputs, one persistent kernel.
// One CTA per (b, cell); 256 threads. Cross-cell sync via per-cell flags.
// ---------------------------------------------------------------------------
__global__ __launch_bounds__(256, 3) void k_fused(const float* __restrict__ feats,
                                                  float* __restrict__ gamma_out,
                                                  float* __restrict__ recon_out) {
    __shared__ float s_sh[9][C];                        // neighbor spix / later fm
    __shared__ float sn_sh[9];
    __shared__ int   cell_sh[9];
    __shared__ int   expect_sh[9];
    __shared__ __align__(16) float pix_sh[C * PITCH];   // later: aff2[9][256]
    __shared__ __align__(16) float aff_sh[9][256];      // aliased as s_acc in reduce

    int blk = blockIdx.x;
    int b = blk / J, j = blk % J;
    int jy = j / JW, jx = j % JW;
    int t = threadIdx.x;
    int wk = t >> 5, lane = t & 31;

    // neighbor table + expected contributor counts (static)
    if (t < 9) {
        int dy = t / 3 - 1, dx = t % 3 - 1;
        int ny = jy + dy, nx = jx + dx;
        int nc = (ny >= 0 && ny < JH && nx >= 0 && nx < JW) ? ny * JW + nx : -1;
        cell_sh[t] = nc;
        int ex = 0;
        if (nc >= 0) {
            int cy = 3 - (ny == 0) - (ny == JH - 1);
            int cx = 3 - (nx == 0) - (nx == JW - 1);
            ex = cy * cx;
        }
        expect_sh[t] = ex;
    }

    // load pixel features ONCE; keep in registers + smem
    int py = t >> 4, px = t & 15;
    int y = jy * 16 + py, x = jx * 16 + px;
    int n = y * W + x;
    const float* fp = feats + (size_t)b * C * HW + n;
    float f[C];
    #pragma unroll
    for (int c = 0; c < C; c++) {
        f[c] = fp[c * HW];
        pix_sh[c * PITCH + t] = f[c];
    }
    float fn = 0.0f;
    #pragma unroll
    for (int c = 0; c < C; c++) fn += f[c] * f[c];

    // zero own cell's slots 1..10; write slot-0 den
    if (t < C) {
        #pragma unroll
        for (int s = 1; s < SLOTS; s++) g_num[s][(b * J + j) * C + t] = 0.0f;
    }
    if (t == C) {
        #pragma unroll
        for (int s = 1; s < SLOTS; s++) g_den[s][b * J + j] = 0.0f;
        g_den[0][b * J + j] = 256.0f;   // so num/(den+eps) == cell mean exactly
    }
    __syncthreads();   // pix_sh + tables ready

    // slot-0 num = per-channel sum over own 16x16 cell (warp slices -> tree)
    {
        const float* pr = &pix_sh[lane * PITCH + wk * 32];
        float ms = 0.0f;
        #pragma unroll
        for (int i = 0; i < 32; i += 4) {
            float4 v = *(const float4*)&pr[i];
            ms += (v.x + v.y) + (v.z + v.w);
        }
        ((float*)aff_sh)[wk * 32 + lane] = ms;
        __syncthreads();
        if (wk == 0) {
            float s = 0.0f;
            #pragma unroll
            for (int w2 = 0; w2 < 8; w2++) s += ((float*)aff_sh)[w2 * 32 + lane];
            g_num[0][(b * J + j) * C + lane] = s;
        }
    }
    __threadfence();          // each thread makes its init stores visible
    __syncthreads();
    if (t == 0) atomicAdd(&g_flag[0][b * J + j], 1u);   // publish slot 0

    float a[9];               // own-pixel affinities (persist to finale)

    for (int it = 0; it < NITER; it++) {
        // ---- phase 0: wait for + load neighbor spix from slot `it` ----
        for (int k = wk; k < 9; k += 8) {
            int nc = cell_sh[k];
            float sv = 0.0f;
            if (nc >= 0) {
                int idx = b * J + nc;
                if (lane == 0) {
                    unsigned ex = (it == 0) ? 1u : (unsigned)expect_sh[k];
                    poll_flag(&g_flag[it][idx], ex);
                }
                __syncwarp();
                sv = __ldcg(&g_num[it][idx * C + lane]) /
                     (__ldcg(&g_den[it][idx]) + 1e-16f);
            }
            s_sh[k][lane] = sv;
            float sq = sv * sv;
            #pragma unroll
            for (int o = 16; o; o >>= 1) sq += __shfl_xor_sync(0xffffffffu, sq, o);
            if (lane == 0) sn_sh[k] = sq;
        }
        __syncthreads();

        // ---- phase 1: distances (LDS.128 broadcast) + masked softmax ----
        float dist[9];
        #pragma unroll
        for (int k = 0; k < 9; k++) {
            const float4* s4 = (const float4*)s_sh[k];
            float d0 = 0, d1 = 0, d2 = 0, d3 = 0;
            #pragma unroll
            for (int c4 = 0; c4 < 8; c4++) {
                float4 sv = s4[c4];
                d0 += f[4 * c4 + 0] * sv.x;
                d1 += f[4 * c4 + 1] * sv.y;
                d2 += f[4 * c4 + 2] * sv.z;
                d3 += f[4 * c4 + 3] * sv.w;
            }
            dist[k] = fn - 2.0f * ((d0 + d1) + (d2 + d3)) + sn_sh[k];
        }
        float m = 3.0e38f;
        #pragma unroll
        for (int k = 0; k < 9; k++)
            if (cell_sh[k] >= 0) m = fminf(m, dist[k]);
        float sum = 0.0f;
        #pragma unroll
        for (int k = 0; k < 9; k++) {
            a[k] = (cell_sh[k] >= 0) ? __expf(m - dist[k]) : 0.0f;
            sum += a[k];
        }
        float inv = 1.0f / sum;
        #pragma unroll
        for (int k = 0; k < 9; k++) {
            a[k] *= inv;
            aff_sh[k][t] = a[k];
        }
        __syncthreads();

        // ---- phase 2: warp-slice accumulation (lane = channel) ----
        float acc[9];
        #pragma unroll
        for (int k = 0; k < 9; k++) acc[k] = 0.0f;
        {
            int p0 = wk * 32;
            const float* pr = &pix_sh[lane * PITCH + p0];
            #pragma unroll
            for (int i = 0; i < 32; i += 4) {
                float4 pv = *(const float4*)&pr[i];
                #pragma unroll
                for (int k = 0; k < 9; k++) {
                    float4 av = *(const float4*)&aff_sh[k][p0 + i];   // broadcast
                    acc[k] += av.x * pv.x + av.y * pv.y + av.z * pv.z + av.w * pv.w;
                }
            }
        }
        // denominators (read aff_sh before it is aliased); lane 0 holds result
        float dreg[2] = {0.0f, 0.0f};
        {
            int nd = 0;
            for (int k = wk; k < 9; k += 8) {
                float d = 0.0f;
                #pragma unroll
                for (int i2 = 0; i2 < 8; i2++) d += aff_sh[k][lane + (i2 << 5)];
                #pragma unroll
                for (int o = 16; o; o >>= 1) d += __shfl_xor_sync(0xffffffffu, d, o);
                dreg[nd++] = d;
            }
        }
        __syncthreads();                       // aff_sh + pix_sh reads done
        if (it == NITER - 1) {                 // stash affinities for the finale
            #pragma unroll
            for (int k = 0; k < 9; k++) pix_sh[k * 256 + t] = a[k];
        }
        float* s_acc = (float*)aff_sh;         // [8][9][32]
        #pragma unroll
        for (int k = 0; k < 9; k++)
            s_acc[(wk * 9 + k) * 32 + lane] = acc[k];
        __syncthreads();

        // ---- tree reduce + atomics + publish flags for slot it+1 ----
        {
            int nd = 0;
            for (int k = wk; k < 9; k += 8) {
                int nc = cell_sh[k];
                float dv = dreg[nd++];
                if (nc >= 0) {
                    float v = 0.0f;
                    #pragma unroll
                    for (int w2 = 0; w2 < 8; w2++)
                        v += s_acc[(w2 * 9 + k) * 32 + lane];
                    atomicAdd(&g_num[it + 1][(b * J + nc) * C + lane], v);
                    if (lane == 0) atomicAdd(&g_den[it + 1][b * J + nc], dv);
                }
            }
        }
        __threadfence();                       // make this warp's atomics visible
        for (int k = wk; k < 9; k += 8) {
            int nc = cell_sh[k];
            if (nc >= 0 && lane == 0) atomicAdd(&g_flag[it + 1][b * J + nc], 1u);
        }
    }

    // =======================================================================
    // Finale (merged k_final): gamma first (no dependency on slot 10), then fm
    // + recon. aff2 = pix_sh[0 .. 9*256).
    // =======================================================================
    const float* aff2 = pix_sh;
    {
        int q = t & 63, jr = t >> 6;
        int r = q >> 2, colq = q & 3;
        size_t rowoff = (size_t)(jy * 16 + r) * W + jx * 16 + colq * 4;
        #pragma unroll 4
        for (int i = 0; i < 48; i++) {
            int jv  = jr + (i << 2);
            int jjy = jv >> 4, jjx = jv & 15;
            int ddy = jjy - jy, ddx = jjx - jx;
            float4 v = make_float4(0.f, 0.f, 0.f, 0.f);
            if (ddy >= -1 && ddy <= 1 && ddx >= -1 && ddx <= 1) {
                int k = (ddy + 1) * 3 + (ddx + 1);
                v = *(const float4*)&aff2[k * 256 + r * 16 + colq * 4];
            }
            *(float4*)&gamma_out[((size_t)(b * J + jv)) * N + rowoff] = v;
        }
    }

    // fm = num[10]/(den[10]+1e-6), gated on slot-10 flags
    for (int k = wk; k < 9; k += 8) {
        int nc = cell_sh[k];
        float fv = 0.0f;
        if (nc >= 0) {
            int idx = b * J + nc;
            if (lane == 0) poll_flag(&g_flag[NITER][idx], (unsigned)expect_sh[k]);
            __syncwarp();
            fv = __ldcg(&g_num[NITER][idx * C + lane]) /
                 (__ldcg(&g_den[NITER][idx]) + 1e-6f);
        }
        s_sh[k][lane] = fv;
    }
    __syncthreads();

    // recon[b,c,n] = sum_k a[k] * fm[cell_k][c]
    float rec[C];
    #pragma unroll
    for (int c = 0; c < C; c++) rec[c] = 0.0f;
    #pragma unroll
    for (int k = 0; k < 9; k++) {
        const float4* s4 = (const float4*)s_sh[k];
        float ak = a[k];
        #pragma unroll
        for (int c4 = 0; c4 < 8; c4++) {
            float4 sv = s4[c4];
            rec[4 * c4 + 0] += ak * sv.x;
            rec[4 * c4 + 1] += ak * sv.y;
            rec[4 * c4 + 2] += ak * sv.z;
            rec[4 * c4 + 3] += ak * sv.w;
        }
    }
    #pragma unroll
    for (int c = 0; c < C; c++)
        recon_out[((size_t)(b * C + c) * H + y) * W + x] = rec[c];
}

// ---------------------------------------------------------------------------
extern "C" void kernel_launch(void* const* d_in, const int* in_sizes, int n_in,
                              void* d_out, int out_size) {
    (void)in_sizes; (void)n_in; (void)out_size;
    const float* feats = (const float*)d_in[0];
    float* gamma = (float*)d_out;
    float* recon = gamma + (size_t)B * J * N;

    k_reset<<<(SLOTS * B * J + 255) / 256, 256>>>();
    k_fused<<<NB, 256>>>(feats, gamma, recon);
}

// round 8
// speedup vs baseline: 1.5605x; 1.0038x over previous
#include <cuda_runtime.h>

namespace {
constexpr int B  = 2;
constexpr int C  = 32;
constexpr int H  = 192;
constexpr int W  = 256;
constexpr int JH = 12;
constexpr int JW = 16;
constexpr int J  = JH * JW;      // 192
constexpr int N  = H * W;        // 49152
constexpr int HW = H * W;
constexpr int NITER = 10;
constexpr int SLOTS = NITER + 1; // slot 0 = init, slots 1..10 = iteration results
constexpr int PITCH = 260;       // 260*4B = 16B-aligned rows; LDS.128 conflict-free
constexpr int NB = B * J;        // 384 blocks, co-resident at 3 CTAs/SM (148*3=444)
}

// Persistent scratch (device globals; no allocation allowed)
__device__ float    g_num[SLOTS][B * J * C];
__device__ float    g_den[SLOTS][B * J];
__device__ unsigned g_flag[SLOTS][B * J];

// ---------------------------------------------------------------------------
// Packed f32x2 helpers (Blackwell packed FP32: 2 FMAs per instruction)
// ---------------------------------------------------------------------------
__device__ __forceinline__ void ffma2(unsigned long long& d,
                                      unsigned long long a, unsigned long long b) {
    asm("fma.rn.f32x2 %0, %1, %2, %0;" : "+l"(d) : "l"(a), "l"(b));
}
__device__ __forceinline__ float f2sum(unsigned long long v) {
    float lo, hi;
    asm("mov.b64 {%0, %1}, %2;" : "=f"(lo), "=f"(hi) : "l"(v));
    return lo + hi;
}
__device__ __forceinline__ void f2unpack(unsigned long long v, float& lo, float& hi) {
    asm("mov.b64 {%0, %1}, %2;" : "=f"(lo), "=f"(hi) : "l"(v));
}
__device__ __forceinline__ unsigned long long f2pack(float lo, float hi) {
    unsigned long long r;
    asm("mov.b64 %0, {%1, %2};" : "=l"(r) : "f"(lo), "f"(hi));
    return r;
}

// ---------------------------------------------------------------------------
// Reset the dataflow flags each replay (kernel boundary orders it vs k_fused).
// ---------------------------------------------------------------------------
__global__ void k_reset() {
    int i = blockIdx.x * blockDim.x + threadIdx.x;
    if (i < SLOTS * B * J) (&g_flag[0][0])[i] = 0u;
}

// All lanes poll with acquire (each lane gets its own ordered view; no fence gap)
__device__ __forceinline__ void poll_flag(const unsigned* p, unsigned expect) {
    unsigned v;
    do {
        asm volatile("ld.acquire.gpu.u32 %0, [%1];" : "=r"(v) : "l"(p) : "memory");
        if (v >= expect) return;
        __nanosleep(64);
    } while (true);
}

// ---------------------------------------------------------------------------
// Fully fused SSN: init + 10 iterations + final outputs, one persistent kernel.
// One CTA per (b, cell); 256 threads. Cross-cell sync via per-cell flags.
// ---------------------------------------------------------------------------
__global__ __launch_bounds__(256, 3) void k_fused(const float* __restrict__ feats,
                                                  float* __restrict__ gamma_out,
                                                  float* __restrict__ recon_out) {
    __shared__ __align__(16) float s_sh[9][C];          // neighbor spix / later fm
    __shared__ float sn_sh[9];
    __shared__ int   cell_sh[9];
    __shared__ int   expect_sh[9];
    __shared__ __align__(16) float pix_sh[C * PITCH];   // later: aff2[9][256]
    __shared__ __align__(16) float aff_sh[9][256];      // aliased as s_acc in reduce

    int blk = blockIdx.x;
    int b = blk / J, j = blk % J;
    int jy = j / JW, jx = j % JW;
    int bJ = b * J;
    int t = threadIdx.x;
    int wk = t >> 5, lane = t & 31;

    // neighbor table + expected contributor counts (static)
    if (t < 9) {
        int dy = t / 3 - 1, dx = t % 3 - 1;
        int ny = jy + dy, nx = jx + dx;
        int nc = (ny >= 0 && ny < JH && nx >= 0 && nx < JW) ? ny * JW + nx : -1;
        cell_sh[t] = nc;
        int ex = 0;
        if (nc >= 0) {
            int cy = 3 - (ny == 0) - (ny == JH - 1);
            int cx = 3 - (nx == 0) - (nx == JW - 1);
            ex = cy * cx;
        }
        expect_sh[t] = ex;
    }

    // load pixel features ONCE; pack into f32x2 registers + stage in smem
    int py = t >> 4, px = t & 15;
    int y = jy * 16 + py, x = jx * 16 + px;
    int n = y * W + x;
    const float* fp = feats + (size_t)b * C * HW + n;
    unsigned long long f2[16];
    #pragma unroll
    for (int i = 0; i < 16; i++) {
        float lo = fp[(2 * i) * HW];
        float hi = fp[(2 * i + 1) * HW];
        pix_sh[(2 * i) * PITCH + t]     = lo;
        pix_sh[(2 * i + 1) * PITCH + t] = hi;
        f2[i] = f2pack(lo, hi);
    }
    unsigned long long fn2 = 0ull;
    #pragma unroll
    for (int i = 0; i < 16; i++) ffma2(fn2, f2[i], f2[i]);
    float fn = f2sum(fn2);

    // zero own cell's slots 1..10; write slot-0 den
    if (t < C) {
        #pragma unroll
        for (int s = 1; s < SLOTS; s++) g_num[s][(bJ + j) * C + t] = 0.0f;
    }
    if (t == C) {
        #pragma unroll
        for (int s = 1; s < SLOTS; s++) g_den[s][bJ + j] = 0.0f;
        g_den[0][bJ + j] = 256.0f;   // so num/(den+eps) == cell mean exactly
    }
    __syncthreads();   // pix_sh + tables ready

    // slot-0 num = per-channel sum over own 16x16 cell (warp slices -> tree)
    {
        const float* pr = &pix_sh[lane * PITCH + wk * 32];
        float ms = 0.0f;
        #pragma unroll
        for (int i = 0; i < 32; i += 4) {
            float4 v = *(const float4*)&pr[i];
            ms += (v.x + v.y) + (v.z + v.w);
        }
        ((float*)aff_sh)[wk * 32 + lane] = ms;
        __syncthreads();
        if (wk == 0) {
            float s = 0.0f;
            #pragma unroll
            for (int w2 = 0; w2 < 8; w2++) s += ((float*)aff_sh)[w2 * 32 + lane];
            g_num[0][(bJ + j) * C + lane] = s;
        }
    }
    __threadfence();
    __syncthreads();
    if (t == 0) atomicAdd(&g_flag[0][bJ + j], 1u);   // publish slot 0

    float a[9];               // own-pixel affinities (persist to finale)

    for (int it = 0; it < NITER; it++) {
        // ---- phase 0: wait for + load neighbor spix from slot `it` ----
        for (int k = wk; k < 9; k += 8) {
            int nc = cell_sh[k];
            float sv = 0.0f;
            if (nc >= 0) {
                int idx = bJ + nc;
                unsigned ex = (it == 0) ? 1u : (unsigned)expect_sh[k];
                poll_flag(&g_flag[it][idx], ex);             // all lanes, acquire
                sv = __ldcg(&g_num[it][idx * C + lane]) /
                     (__ldcg(&g_den[it][idx]) + 1e-16f);
            }
            s_sh[k][lane] = sv;
            float sq = sv * sv;
            #pragma unroll
            for (int o = 16; o; o >>= 1) sq += __shfl_xor_sync(0xffffffffu, sq, o);
            if (lane == 0) sn_sh[k] = sq;
        }
        __syncthreads();

        // ---- phase 1: distances (f32x2 FMA, LDS.128 broadcast) + softmax ----
        float dist[9];
        #pragma unroll
        for (int k = 0; k < 9; k++) {
            const ulonglong2* s2 = (const ulonglong2*)s_sh[k];
            unsigned long long d2 = 0ull;
            #pragma unroll
            for (int c4 = 0; c4 < 8; c4++) {
                ulonglong2 sv = s2[c4];
                ffma2(d2, f2[2 * c4],     sv.x);
                ffma2(d2, f2[2 * c4 + 1], sv.y);
            }
            dist[k] = fn - 2.0f * f2sum(d2) + sn_sh[k];
        }
        float m = 3.0e38f;
        #pragma unroll
        for (int k = 0; k < 9; k++)
            if (cell_sh[k] >= 0) m = fminf(m, dist[k]);
        float sum = 0.0f;
        #pragma unroll
        for (int k = 0; k < 9; k++) {
            a[k] = (cell_sh[k] >= 0) ? __expf(m - dist[k]) : 0.0f;
            sum += a[k];
        }
        float inv = 1.0f / sum;
        #pragma unroll
        for (int k = 0; k < 9; k++) {
            a[k] *= inv;
            aff_sh[k][t] = a[k];
        }
        __syncthreads();

        // ---- phase 2: warp-slice accumulation (lane = channel), f32x2 ----
        unsigned long long acc2[9];
        #pragma unroll
        for (int k = 0; k < 9; k++) acc2[k] = 0ull;
        {
            int p0 = wk * 32;
            const float* pr = &pix_sh[lane * PITCH + p0];
            #pragma unroll
            for (int i = 0; i < 32; i += 4) {
                ulonglong2 pv = *(const ulonglong2*)&pr[i];
                #pragma unroll
                for (int k = 0; k < 9; k++) {
                    ulonglong2 av = *(const ulonglong2*)&aff_sh[k][p0 + i];  // bcast
                    ffma2(acc2[k], av.x, pv.x);
                    ffma2(acc2[k], av.y, pv.y);
                }
            }
        }
        // denominators (read aff_sh before it is aliased); lane 0 holds result
        float dreg[2] = {0.0f, 0.0f};
        {
            int nd = 0;
            for (int k = wk; k < 9; k += 8) {
                float d = 0.0f;
                #pragma unroll
                for (int i2 = 0; i2 < 8; i2++) d += aff_sh[k][lane + (i2 << 5)];
                #pragma unroll
                for (int o = 16; o; o >>= 1) d += __shfl_xor_sync(0xffffffffu, d, o);
                dreg[nd++] = d;
            }
        }
        __syncthreads();                       // aff_sh + pix_sh reads done
        if (it == NITER - 1) {                 // stash affinities for the finale
            #pragma unroll
            for (int k = 0; k < 9; k++) pix_sh[k * 256 + t] = a[k];
        }
        float* s_acc = (float*)aff_sh;         // [8][9][32]
        #pragma unroll
        for (int k = 0; k < 9; k++)
            s_acc[(wk * 9 + k) * 32 + lane] = f2sum(acc2[k]);
        __syncthreads();

        // ---- tree reduce + atomics + publish flags for slot it+1 ----
        {
            int nd = 0;
            for (int k = wk; k < 9; k += 8) {
                int nc = cell_sh[k];
                float dv = dreg[nd++];
                if (nc >= 0) {
                    float v = 0.0f;
                    #pragma unroll
                    for (int w2 = 0; w2 < 8; w2++)
                        v += s_acc[(w2 * 9 + k) * 32 + lane];
                    atomicAdd(&g_num[it + 1][(bJ + nc) * C + lane], v);
                    if (lane == 0) atomicAdd(&g_den[it + 1][bJ + nc], dv);
                }
            }
        }
        __threadfence();                       // make this warp's atomics visible
        for (int k = wk; k < 9; k += 8) {
            int nc = cell_sh[k];
            if (nc >= 0 && lane == 0) atomicAdd(&g_flag[it + 1][bJ + nc], 1u);
        }
    }

    // =======================================================================
    // Finale: gamma first (depends only on stashed aff), then fm + recon.
    // =======================================================================
    const float* aff2 = pix_sh;
    {
        int q = t & 63, jr = t >> 6;
        int r = q >> 2, colq = q & 3;
        size_t rowoff = (size_t)(jy * 16 + r) * W + jx * 16 + colq * 4;
        #pragma unroll 4
        for (int i = 0; i < 48; i++) {
            int jv  = jr + (i << 2);
            int jjy = jv >> 4, jjx = jv & 15;
            int ddy = jjy - jy, ddx = jjx - jx;
            float4 v = make_float4(0.f, 0.f, 0.f, 0.f);
            if (ddy >= -1 && ddy <= 1 && ddx >= -1 && ddx <= 1) {
                int k = (ddy + 1) * 3 + (ddx + 1);
                v = *(const float4*)&aff2[k * 256 + r * 16 + colq * 4];
            }
            __stcs((float4*)&gamma_out[((size_t)(bJ + jv)) * N + rowoff], v);
        }
    }

    // fm = num[10]/(den[10]+1e-6), gated on slot-10 flags
    for (int k = wk; k < 9; k += 8) {
        int nc = cell_sh[k];
        float fv = 0.0f;
        if (nc >= 0) {
            int idx = bJ + nc;
            poll_flag(&g_flag[NITER][idx], (unsigned)expect_sh[k]);
            fv = __ldcg(&g_num[NITER][idx * C + lane]) /
                 (__ldcg(&g_den[NITER][idx]) + 1e-6f);
        }
        s_sh[k][lane] = fv;
    }
    __syncthreads();

    // recon[b,c,n] = sum_k a[k] * fm[cell_k][c]   (f32x2)
    unsigned long long rec2[16];
    #pragma unroll
    for (int i = 0; i < 16; i++) rec2[i] = 0ull;
    #pragma unroll
    for (int k = 0; k < 9; k++) {
        unsigned long long ak2 = f2pack(a[k], a[k]);
        const ulonglong2* s2 = (const ulonglong2*)s_sh[k];
        #pragma unroll
        for (int c4 = 0; c4 < 8; c4++) {
            ulonglong2 sv = s2[c4];
            ffma2(rec2[2 * c4],     ak2, sv.x);
            ffma2(rec2[2 * c4 + 1], ak2, sv.y);
        }
    }
    #pragma unroll
    for (int i = 0; i < 16; i++) {
        float lo, hi;
        f2unpack(rec2[i], lo, hi);
        __stcs(&recon_out[((size_t)(b * C + 2 * i) * H + y) * W + x], lo);
        __stcs(&recon_out[((size_t)(b * C + 2 * i + 1) * H + y) * W + x], hi);
    }
}

// ---------------------------------------------------------------------------
extern "C" void kernel_launch(void* const* d_in, const int* in_sizes, int n_in,
                              void* d_out, int out_size) {
    (void)in_sizes; (void)n_in; (void)out_size;
    const float* feats = (const float*)d_in[0];
    float* gamma = (float*)d_out;
    float* recon = gamma + (size_t)B * J * N;

    k_reset<<<(SLOTS * B * J + 255) / 256, 256>>>();
    k_fused<<<NB, 256>>>(feats, gamma, recon);
}

// round 9
// speedup vs baseline: 1.6596x; 1.0635x over previous
#include <cuda_runtime.h>

namespace {
constexpr int B  = 2;
constexpr int C  = 32;
constexpr int H  = 192;
constexpr int W  = 256;
constexpr int JH = 12;
constexpr int JW = 16;
constexpr int J  = JH * JW;      // 192
constexpr int N  = H * W;        // 49152
constexpr int HW = H * W;
constexpr int NITER = 10;
constexpr int SLOTS = NITER + 1; // slot 0 = init, slots 1..10 = iteration results
constexpr int PITCH = 260;       // 260*4B = 16B-aligned rows; LDS.128 conflict-free
constexpr int NB = B * J;        // 384 blocks; co-resident (4 CTAs/SM * 148 = 592)
}

// Persistent scratch (device globals; no allocation allowed)
__device__ float    g_num[SLOTS][B * J * C];
__device__ float    g_den[SLOTS][B * J];
__device__ unsigned g_flag[SLOTS][B * J];

// ---------------------------------------------------------------------------
// Packed f32x2 helpers (Blackwell packed FP32: 2 FMAs per instruction)
// ---------------------------------------------------------------------------
__device__ __forceinline__ void ffma2(unsigned long long& d,
                                      unsigned long long a, unsigned long long b) {
    asm("fma.rn.f32x2 %0, %1, %2, %0;" : "+l"(d) : "l"(a), "l"(b));
}
__device__ __forceinline__ float f2sum(unsigned long long v) {
    float lo, hi;
    asm("mov.b64 {%0, %1}, %2;" : "=f"(lo), "=f"(hi) : "l"(v));
    return lo + hi;
}
__device__ __forceinline__ void f2unpack(unsigned long long v, float& lo, float& hi) {
    asm("mov.b64 {%0, %1}, %2;" : "=f"(lo), "=f"(hi) : "l"(v));
}
__device__ __forceinline__ unsigned long long f2pack(float lo, float hi) {
    unsigned long long r;
    asm("mov.b64 %0, {%1, %2};" : "=l"(r) : "f"(lo), "f"(hi));
    return r;
}

// ---------------------------------------------------------------------------
// Reset the dataflow flags each replay (kernel boundary orders it vs k_fused).
// ---------------------------------------------------------------------------
__global__ void k_reset() {
    int i = blockIdx.x * blockDim.x + threadIdx.x;
    if (i < SLOTS * B * J) (&g_flag[0][0])[i] = 0u;
}

// All lanes poll with acquire (each lane gets its own ordered view; no fence gap)
__device__ __forceinline__ void poll_flag(const unsigned* p, unsigned expect) {
    unsigned v;
    do {
        asm volatile("ld.acquire.gpu.u32 %0, [%1];" : "=r"(v) : "l"(p) : "memory");
        if (v >= expect) return;
        __nanosleep(64);
    } while (true);
}

// ---------------------------------------------------------------------------
// Fully fused SSN: init + 10 iterations + final outputs, one persistent kernel.
// One CTA per (b, cell); 256 threads. Cross-cell sync via per-cell flags.
// 4 CTAs/SM (64-reg cap): pixel features live in smem only; phase 1 repacks
// its pixel's channels from pix_sh on the fly.
// ---------------------------------------------------------------------------
__global__ __launch_bounds__(256, 4) void k_fused(const float* __restrict__ feats,
                                                  float* __restrict__ gamma_out,
                                                  float* __restrict__ recon_out) {
    __shared__ __align__(16) float s_sh[9][C];          // neighbor spix / later fm
    __shared__ float sn_sh[9];
    __shared__ int   cell_sh[9];
    __shared__ int   expect_sh[9];
    __shared__ __align__(16) float pix_sh[C * PITCH];   // later: aff2[9][256]
    __shared__ __align__(16) float aff_sh[9][256];      // aliased as s_acc in reduce

    int blk = blockIdx.x;
    int b = blk / J, j = blk % J;
    int jy = j / JW, jx = j % JW;
    int bJ = b * J;
    int t = threadIdx.x;
    int wk = t >> 5, lane = t & 31;

    // neighbor table + expected contributor counts (static)
    if (t < 9) {
        int dy = t / 3 - 1, dx = t % 3 - 1;
        int ny = jy + dy, nx = jx + dx;
        int nc = (ny >= 0 && ny < JH && nx >= 0 && nx < JW) ? ny * JW + nx : -1;
        cell_sh[t] = nc;
        int ex = 0;
        if (nc >= 0) {
            int cy = 3 - (ny == 0) - (ny == JH - 1);
            int cx = 3 - (nx == 0) - (nx == JW - 1);
            ex = cy * cx;
        }
        expect_sh[t] = ex;
    }

    // load pixel features ONCE into smem; compute |f|^2 (fn persists, 1 reg)
    int py = t >> 4, px = t & 15;
    int y = jy * 16 + py, x = jx * 16 + px;
    int n = y * W + x;
    const float* fp = feats + (size_t)b * C * HW + n;
    float fn;
    {
        unsigned long long fn2 = 0ull;
        #pragma unroll
        for (int i = 0; i < 16; i++) {
            float lo = fp[(2 * i) * HW];
            float hi = fp[(2 * i + 1) * HW];
            pix_sh[(2 * i) * PITCH + t]     = lo;
            pix_sh[(2 * i + 1) * PITCH + t] = hi;
            unsigned long long v = f2pack(lo, hi);
            ffma2(fn2, v, v);
        }
        fn = f2sum(fn2);
    }

    // zero own cell's slots 1..10; write slot-0 den
    if (t < C) {
        #pragma unroll
        for (int s = 1; s < SLOTS; s++) g_num[s][(bJ + j) * C + t] = 0.0f;
    }
    if (t == C) {
        #pragma unroll
        for (int s = 1; s < SLOTS; s++) g_den[s][bJ + j] = 0.0f;
        g_den[0][bJ + j] = 256.0f;   // so num/(den+eps) == cell mean exactly
    }
    __syncthreads();   // pix_sh + tables ready

    // slot-0 num = per-channel sum over own 16x16 cell (warp slices -> tree)
    {
        const float* pr = &pix_sh[lane * PITCH + wk * 32];
        float ms = 0.0f;
        #pragma unroll
        for (int i = 0; i < 32; i += 4) {
            float4 v = *(const float4*)&pr[i];
            ms += (v.x + v.y) + (v.z + v.w);
        }
        ((float*)aff_sh)[wk * 32 + lane] = ms;
        __syncthreads();
        if (wk == 0) {
            float s = 0.0f;
            #pragma unroll
            for (int w2 = 0; w2 < 8; w2++) s += ((float*)aff_sh)[w2 * 32 + lane];
            g_num[0][(bJ + j) * C + lane] = s;
        }
    }
    __threadfence();
    __syncthreads();
    if (t == 0) atomicAdd(&g_flag[0][bJ + j], 1u);   // publish slot 0

    float a[9];               // own-pixel affinities (persist to finale)

    for (int it = 0; it < NITER; it++) {
        // ---- phase 0: wait for + load neighbor spix from slot `it` ----
        for (int k = wk; k < 9; k += 8) {
            int nc = cell_sh[k];
            float sv = 0.0f;
            if (nc >= 0) {
                int idx = bJ + nc;
                unsigned ex = (it == 0) ? 1u : (unsigned)expect_sh[k];
                poll_flag(&g_flag[it][idx], ex);             // all lanes, acquire
                sv = __ldcg(&g_num[it][idx * C + lane]) /
                     (__ldcg(&g_den[it][idx]) + 1e-16f);
            }
            s_sh[k][lane] = sv;
            float sq = sv * sv;
            #pragma unroll
            for (int o = 16; o; o >>= 1) sq += __shfl_xor_sync(0xffffffffu, sq, o);
            if (lane == 0) sn_sh[k] = sq;
        }
        __syncthreads();

        // ---- phase 1: distances (f32x2 FMA; f repacked from smem) + softmax ----
        unsigned long long d2[9];
        #pragma unroll
        for (int k = 0; k < 9; k++) d2[k] = 0ull;
        #pragma unroll
        for (int c4 = 0; c4 < 8; c4++) {
            float fa = pix_sh[(4 * c4 + 0) * PITCH + t];
            float fb = pix_sh[(4 * c4 + 1) * PITCH + t];
            float fc = pix_sh[(4 * c4 + 2) * PITCH + t];
            float fd = pix_sh[(4 * c4 + 3) * PITCH + t];
            unsigned long long fx = f2pack(fa, fb);
            unsigned long long fy = f2pack(fc, fd);
            #pragma unroll
            for (int k = 0; k < 9; k++) {
                ulonglong2 sv = ((const ulonglong2*)s_sh[k])[c4];
                ffma2(d2[k], fx, sv.x);
                ffma2(d2[k], fy, sv.y);
            }
        }
        float dist[9];
        #pragma unroll
        for (int k = 0; k < 9; k++)
            dist[k] = fn - 2.0f * f2sum(d2[k]) + sn_sh[k];

        float m = 3.0e38f;
        #pragma unroll
        for (int k = 0; k < 9; k++)
            if (cell_sh[k] >= 0) m = fminf(m, dist[k]);
        float sum = 0.0f;
        #pragma unroll
        for (int k = 0; k < 9; k++) {
            a[k] = (cell_sh[k] >= 0) ? __expf(m - dist[k]) : 0.0f;
            sum += a[k];
        }
        float inv = 1.0f / sum;
        #pragma unroll
        for (int k = 0; k < 9; k++) {
            a[k] *= inv;
            aff_sh[k][t] = a[k];
        }
        __syncthreads();

        // ---- phase 2: warp-slice accumulation (lane = channel), f32x2 ----
        unsigned long long acc2[9];
        #pragma unroll
        for (int k = 0; k < 9; k++) acc2[k] = 0ull;
        {
            int p0 = wk * 32;
            const float* pr = &pix_sh[lane * PITCH + p0];
            #pragma unroll
            for (int i = 0; i < 32; i += 4) {
                ulonglong2 pv = *(const ulonglong2*)&pr[i];
                #pragma unroll
                for (int k = 0; k < 9; k++) {
                    ulonglong2 av = *(const ulonglong2*)&aff_sh[k][p0 + i];  // bcast
                    ffma2(acc2[k], av.x, pv.x);
                    ffma2(acc2[k], av.y, pv.y);
                }
            }
        }
        // denominators (read aff_sh before it is aliased); lane 0 holds result
        float dreg[2] = {0.0f, 0.0f};
        {
            int nd = 0;
            for (int k = wk; k < 9; k += 8) {
                float d = 0.0f;
                #pragma unroll
                for (int i2 = 0; i2 < 8; i2++) d += aff_sh[k][lane + (i2 << 5)];
                #pragma unroll
                for (int o = 16; o; o >>= 1) d += __shfl_xor_sync(0xffffffffu, d, o);
                dreg[nd++] = d;
            }
        }
        __syncthreads();                       // aff_sh + pix_sh reads done
        if (it == NITER - 1) {                 // stash affinities for the finale
            #pragma unroll
            for (int k = 0; k < 9; k++) pix_sh[k * 256 + t] = a[k];
        }
        float* s_acc = (float*)aff_sh;         // [8][9][32]
        #pragma unroll
        for (int k = 0; k < 9; k++)
            s_acc[(wk * 9 + k) * 32 + lane] = f2sum(acc2[k]);
        __syncthreads();

        // ---- tree reduce + atomics + publish flags for slot it+1 ----
        {
            int nd = 0;
            for (int k = wk; k < 9; k += 8) {
                int nc = cell_sh[k];
                float dv = dreg[nd++];
                if (nc >= 0) {
                    float v = 0.0f;
                    #pragma unroll
                    for (int w2 = 0; w2 < 8; w2++)
                        v += s_acc[(w2 * 9 + k) * 32 + lane];
                    atomicAdd(&g_num[it + 1][(bJ + nc) * C + lane], v);
                    if (lane == 0) atomicAdd(&g_den[it + 1][bJ + nc], dv);
                }
            }
        }
        __threadfence();                       // make this warp's atomics visible
        for (int k = wk; k < 9; k += 8) {
            int nc = cell_sh[k];
            if (nc >= 0 && lane == 0) atomicAdd(&g_flag[it + 1][bJ + nc], 1u);
        }
    }

    // =======================================================================
    // Finale: gamma first (depends only on stashed aff), then fm + recon.
    // =======================================================================
    const float* aff2 = pix_sh;
    {
        int q = t & 63, jr = t >> 6;
        int r = q >> 2, colq = q & 3;
        size_t rowoff = (size_t)(jy * 16 + r) * W + jx * 16 + colq * 4;
        #pragma unroll 4
        for (int i = 0; i < 48; i++) {
            int jv  = jr + (i << 2);
            int jjy = jv >> 4, jjx = jv & 15;
            int ddy = jjy - jy, ddx = jjx - jx;
            float4 v = make_float4(0.f, 0.f, 0.f, 0.f);
            if (ddy >= -1 && ddy <= 1 && ddx >= -1 && ddx <= 1) {
                int k = (ddy + 1) * 3 + (ddx + 1);
                v = *(const float4*)&aff2[k * 256 + r * 16 + colq * 4];
            }
            __stcs((float4*)&gamma_out[((size_t)(bJ + jv)) * N + rowoff], v);
        }
    }

    // fm = num[10]/(den[10]+1e-6), gated on slot-10 flags
    for (int k = wk; k < 9; k += 8) {
        int nc = cell_sh[k];
        float fv = 0.0f;
        if (nc >= 0) {
            int idx = bJ + nc;
            poll_flag(&g_flag[NITER][idx], (unsigned)expect_sh[k]);
            fv = __ldcg(&g_num[NITER][idx * C + lane]) /
                 (__ldcg(&g_den[NITER][idx]) + 1e-6f);
        }
        s_sh[k][lane] = fv;
    }
    __syncthreads();

    // recon[b,c,n] = sum_k a[k] * fm[cell_k][c]   (f32x2)
    unsigned long long rec2[16];
    #pragma unroll
    for (int i = 0; i < 16; i++) rec2[i] = 0ull;
    #pragma unroll
    for (int k = 0; k < 9; k++) {
        unsigned long long ak2 = f2pack(a[k], a[k]);
        const ulonglong2* s2 = (const ulonglong2*)s_sh[k];
        #pragma unroll
        for (int c4 = 0; c4 < 8; c4++) {
            ulonglong2 sv = s2[c4];
            ffma2(rec2[2 * c4],     ak2, sv.x);
            ffma2(rec2[2 * c4 + 1], ak2, sv.y);
        }
    }
    #pragma unroll
    for (int i = 0; i < 16; i++) {
        float lo, hi;
        f2unpack(rec2[i], lo, hi);
        __stcs(&recon_out[((size_t)(b * C + 2 * i) * H + y) * W + x], lo);
        __stcs(&recon_out[((size_t)(b * C + 2 * i + 1) * H + y) * W + x], hi);
    }
}

// ---------------------------------------------------------------------------
extern "C" void kernel_launch(void* const* d_in, const int* in_sizes, int n_in,
                              void* d_out, int out_size) {
    (void)in_sizes; (void)n_in; (void)out_size;
    const float* feats = (const float*)d_in[0];
    float* gamma = (float*)d_out;
    float* recon = gamma + (size_t)B * J * N;

    k_reset<<<(SLOTS * B * J + 255) / 256, 256>>>();
    k_fused<<<NB, 256>>>(feats, gamma, recon);
}